// round 8
// baseline (speedup 1.0000x reference)
#include <cuda_runtime.h>
#include <math.h>
#include <stdint.h>

#define NTOK 16384
#define DDIM 2048
#define NEXP 64
#define CAP  256

// GEMM tiling (int8 limb-emulation via legacy mma.sync, compute_100-compatible)
#define BT   128                  // tokens per CTA
#define KC   32                   // K elements per chunk = one k32 mma step
#define NC   (DDIM / KC)          // 64 chunks
#define A_PLANE_W 1024            // 128 rows x 8 words per limb plane
#define B_PLANE_W 512             // 64 rows x 8 words
#define STAGE_W   (3 * A_PLANE_W + 3 * B_PLANE_W)   // 4608 words = 18 KB

#define SA 1048576.0f             // 2^20 token scale
#define SB 16777216.0f            // 2^24 w_sel scale
#define QCLAMP 8355711.0f         // 127*65536 + 127*256 + 127

// ---------------- scratch (static device globals: allocation-free) ----------------
__device__ __align__(16) float    g_aff[NEXP * NTOK];     // affinity [e][n], 4 MB
__device__ __align__(16) uint32_t g_bq[3 * NC * 512];     // prepacked B limb planes
__device__ int   g_counts[NTOK];
__device__ int   g_sel_idx[NEXP * CAP];
__device__ float g_sel_prob[NEXP * CAP];

// ---------------- quantization helpers ----------------
// returns m (byte0 = limb2); t1 (byte0 = limb1); t2 (byte0 = limb0)
__device__ __forceinline__ void q3s(float a, float scale, int &m, int &t1, int &t2) {
    float af = fminf(fmaxf(a * scale, -QCLAMP), QCLAMP);
    m = __float2int_rn(af);
    int s0 = (m << 24) >> 24;
    t1 = (m - s0) >> 8;
    int s1 = (t1 << 24) >> 24;
    t2 = (t1 - s1) >> 8;
}
__device__ __forceinline__ uint32_t packb0(int a, int b, int c, int d) {
    return __byte_perm(__byte_perm((uint32_t)a, (uint32_t)b, 0x0040),
                       __byte_perm((uint32_t)c, (uint32_t)d, 0x0040), 0x5410);
}
// quantize one float4 and write the three limb words
__device__ __forceinline__ void quant_store(float4 v, float scale,
                                            uint32_t* p0, uint32_t* p1, uint32_t* p2,
                                            uint32_t wi) {
    int mx, t1x, t2x, my, t1y, t2y, mz, t1z, t2z, mw, t1w, t2w;
    q3s(v.x, scale, mx, t1x, t2x);
    q3s(v.y, scale, my, t1y, t2y);
    q3s(v.z, scale, mz, t1z, t2z);
    q3s(v.w, scale, mw, t1w, t2w);
    p0[wi] = packb0(t2x, t2y, t2z, t2w);   // limb0 (high byte)
    p1[wi] = packb0(t1x, t1y, t1z, t1w);   // limb1
    p2[wi] = packb0(mx, my, mz, mw);       // limb2 (low byte)
}
__device__ __forceinline__ void imma(int* d, const uint32_t* a, const uint32_t* b) {
    asm volatile("mma.sync.aligned.m16n8k32.row.col.s32.s8.s8.s32 "
        "{%0,%1,%2,%3}, {%4,%5,%6,%7}, {%8,%9}, {%0,%1,%2,%3};"
        : "+r"(d[0]), "+r"(d[1]), "+r"(d[2]), "+r"(d[3])
        : "r"(a[0]), "r"(a[1]), "r"(a[2]), "r"(a[3]), "r"(b[0]), "r"(b[1]));
}

// ---------------- B prep: quantize w_sel into pre-swizzled limb planes ------------
// element block i = (bid*512 + tid)*4: row = i>>11, word covers d..d+3
__global__ __launch_bounds__(512) void prep_b_kernel(const float* __restrict__ wsel) {
    const int g   = (blockIdx.x * 512 + threadIdx.x) * 4;   // 64 blocks
    const int row = g >> 11;
    const int d0  = g & 2047;
    const int c   = d0 >> 5;
    const int qq  = (d0 >> 2) & 7;
    const uint32_t wi = (uint32_t)(c * 512 + row * 8 + (qq ^ (row & 7)));
    float4 v = *(const float4*)&wsel[(size_t)row * DDIM + d0];
    quant_store(v, SB, g_bq, g_bq + NC * 512, g_bq + 2 * NC * 512, wi);
}

// ---------------- GEMM + output zero-fill + counts reset ----------------
// 512 threads, warp grid 4(m) x 4(n), warp tile 32 tok x 16 exp, mt=2 nt=2.
__global__ __launch_bounds__(512, 1)
void gemm_imma_kernel(const float* __restrict__ tok, float* __restrict__ out,
                      int out_size) {
    __shared__ __align__(16) uint32_t smem[2 * STAGE_W];   // 36 KB

    const int tid  = threadIdx.x;
    const int lane = tid & 31;
    const int w    = tid >> 5;            // 16 warps
    const int bid  = blockIdx.x;
    const int n0   = bid * BT;
    const int gr   = lane >> 2;           // 0..7
    const int ci   = lane & 3;            // 0..3
    const int wm   = (w & 3) * 32;        // warp token base
    const int wn   = (w >> 2) * 16;       // warp expert base
    const int w0   = ci ^ gr;             // swizzled word (k 0..15 half)
    const int w1   = (ci + 4) ^ gr;       // swizzled word (k 16..31 half)

    // ---- folded fill: zero this CTA's slice of out, reset counts, write tail ----
    {
        const long long NE2 = 2LL * NTOK * NEXP;
        float4* o4 = (float4*)out;
        const int base = bid * 4096 + tid;
        float4 z = make_float4(0.f, 0.f, 0.f, 0.f);
        #pragma unroll
        for (int k = 0; k < 8; k++) o4[base + k * 512] = z;
        if (tid < 128) g_counts[bid * 128 + tid] = 0;
        if (bid == 0)
            for (long long i = NE2 + tid; i < out_size; i += 512) out[i] = (float)CAP;
    }

    int hh[2][2][4], md[2][2][4], lo[2][2][4];
    #pragma unroll
    for (int mt = 0; mt < 2; mt++)
        #pragma unroll
        for (int nt = 0; nt < 2; nt++)
            #pragma unroll
            for (int r = 0; r < 4; r++) { hh[mt][nt][r] = 0; md[mt][nt][r] = 0; lo[mt][nt][r] = 0; }

    // staging assignment: r = tid>>3 (0..63), q = tid&7 (k-quad)
    const int rr = tid >> 3;
    const int qq = tid & 7;
    const uint32_t swi  = (uint32_t)(rr * 8 + (qq ^ (rr & 7)));
    const uint32_t swi2 = (uint32_t)((rr + 64) * 8 + (qq ^ (rr & 7)));

    const float* gA0 = &tok[(size_t)(n0 + rr) * DDIM + qq * 4];
    const float* gA1 = &tok[(size_t)(n0 + rr + 64) * DDIM + qq * 4];
    const uint32_t* gB0 = &g_bq[swi];
    const uint32_t* gB1 = &g_bq[NC * 512 + swi];
    const uint32_t* gB2 = &g_bq[2 * NC * 512 + swi];

    float4 rA0 = *(const float4*)gA0;
    float4 rA1 = *(const float4*)gA1;
    uint32_t rB0 = gB0[0], rB1 = gB1[0], rB2 = gB2[0];

    // stage chunk 0 into buffer 0
    {
        uint32_t* sb = smem;
        quant_store(rA0, SA, sb, sb + A_PLANE_W, sb + 2 * A_PLANE_W, swi);
        quant_store(rA1, SA, sb, sb + A_PLANE_W, sb + 2 * A_PLANE_W, swi2);
        uint32_t* pb = sb + 3 * A_PLANE_W;
        pb[swi] = rB0; pb[B_PLANE_W + swi] = rB1; pb[2 * B_PLANE_W + swi] = rB2;
    }
    __syncthreads();

    for (int c = 0; c < NC; c++) {
        // prefetch next chunk into regs
        if (c + 1 < NC) {
            rA0 = *(const float4*)(gA0 + (c + 1) * KC);
            rA1 = *(const float4*)(gA1 + (c + 1) * KC);
            rB0 = gB0[(c + 1) * 512];
            rB1 = gB1[(c + 1) * 512];
            rB2 = gB2[(c + 1) * 512];
        }

        // compute on stage c&1
        {
            const uint32_t* sb = smem + (c & 1) * STAGE_W;
            const uint32_t* pb = sb + 3 * A_PLANE_W;

            uint32_t af[2][3][4];
            #pragma unroll
            for (int mt = 0; mt < 2; mt++) {
                const int r0 = (wm + mt * 16 + gr) * 8;
                #pragma unroll
                for (int L = 0; L < 3; L++) {
                    const uint32_t* p = sb + L * A_PLANE_W;
                    af[mt][L][0] = p[r0 + w0];
                    af[mt][L][1] = p[r0 + 64 + w0];   // +8 rows
                    af[mt][L][2] = p[r0 + w1];
                    af[mt][L][3] = p[r0 + 64 + w1];
                }
            }
            #pragma unroll
            for (int nt = 0; nt < 2; nt++) {
                const int c0 = (wn + nt * 8 + gr) * 8;
                uint32_t bf[3][2];
                #pragma unroll
                for (int L = 0; L < 3; L++) {
                    const uint32_t* p = pb + L * B_PLANE_W;
                    bf[L][0] = p[c0 + w0];
                    bf[L][1] = p[c0 + w1];
                }
                #pragma unroll
                for (int mt = 0; mt < 2; mt++) {
                    imma(hh[mt][nt], af[mt][0], bf[0]);
                    imma(md[mt][nt], af[mt][0], bf[1]);
                    imma(md[mt][nt], af[mt][1], bf[0]);
                    imma(lo[mt][nt], af[mt][0], bf[2]);
                    imma(lo[mt][nt], af[mt][1], bf[1]);
                    imma(lo[mt][nt], af[mt][2], bf[0]);
                }
            }
        }

        // stage next chunk into the other buffer
        if (c + 1 < NC) {
            uint32_t* sn = smem + ((c + 1) & 1) * STAGE_W;
            quant_store(rA0, SA, sn, sn + A_PLANE_W, sn + 2 * A_PLANE_W, swi);
            quant_store(rA1, SA, sn, sn + A_PLANE_W, sn + 2 * A_PLANE_W, swi2);
            uint32_t* pn = sn + 3 * A_PLANE_W;
            pn[swi] = rB0; pn[B_PLANE_W + swi] = rB1; pn[2 * B_PLANE_W + swi] = rB2;
            __syncthreads();
        }
    }

    // epilogue: dequant and write g_aff[e][token]
    #pragma unroll
    for (int mt = 0; mt < 2; mt++) {
        const int tok0 = n0 + wm + mt * 16 + gr;
        #pragma unroll
        for (int nt = 0; nt < 2; nt++) {
            const int e0 = wn + nt * 8 + 2 * ci;
            #pragma unroll
            for (int r = 0; r < 4; r++) {
                float v = fmaf((float)hh[mt][nt][r], 0x1p-12f,
                          fmaf((float)md[mt][nt][r], 0x1p-20f,
                               (float)lo[mt][nt][r] * 0x1p-28f));
                const int tk = tok0 + ((r >> 1) << 3);   // +8 for r=2,3
                const int ee = e0 + (r & 1);
                g_aff[(size_t)ee * NTOK + tk] = v;
            }
        }
    }
}

// ---------------- per-expert top-256 + softmax (exact fp32 radix select) ----------
__device__ __forceinline__ unsigned f2key(float v) {
    unsigned u = __float_as_uint(v);
    return (u & 0x80000000u) ? ~u : (u | 0x80000000u);
}

__global__ __launch_bounds__(256) void topk_kernel(float* __restrict__ out) {
    const int e   = blockIdx.x;
    const int tid = threadIdx.x;
    const float* __restrict__ row = g_aff + (size_t)e * NTOK;

    __shared__ unsigned hist[2048];
    __shared__ unsigned chunksum[257];
    __shared__ unsigned sh_prefix, sh_kneed, sh_bin, sh_above;
    __shared__ int   s_idx[CAP];
    __shared__ float s_val[CAP];
    __shared__ int   tie_buf[64];
    __shared__ int   sel_n, tie_n;
    __shared__ float red[10];

    if (tid == 0) { sh_prefix = 0u; sh_kneed = CAP; sel_n = 0; tie_n = 0; }

    const int      shifts[3]   = {21, 10, 0};
    const unsigned binmask[3]  = {2047u, 2047u, 1023u};
    const unsigned donemask[3] = {0u, 0xFFE00000u, 0xFFFFFC00u};

    for (int r = 0; r < 3; r++) {
        for (int b = tid; b < 2048; b += 256) hist[b] = 0u;
        __syncthreads();

        const unsigned pfx = sh_prefix;
        const unsigned dm  = donemask[r];
        const int      sh  = shifts[r];
        const unsigned bm  = binmask[r];

        #pragma unroll 4
        for (int j = 0; j < NTOK / 256; j++) {
            unsigned key = f2key(row[tid + j * 256]);
            if ((key & dm) == pfx) atomicAdd(&hist[(key >> sh) & bm], 1u);
        }
        __syncthreads();

        unsigned S = 0;
        #pragma unroll
        for (int q = 0; q < 8; q++) S += hist[tid * 8 + q];
        chunksum[tid] = S;
        __syncthreads();
        for (int off = 1; off < 256; off <<= 1) {
            unsigned v = (tid + off < 256) ? chunksum[tid + off] : 0u;
            __syncthreads();
            chunksum[tid] += v;
            __syncthreads();
        }
        const unsigned kneed = sh_kneed;
        unsigned above = (tid < 255) ? chunksum[tid + 1] : 0u;
        for (int b = tid * 8 + 7; b >= tid * 8; b--) {
            unsigned h = hist[b];
            if (kneed > above && kneed <= above + h) { sh_bin = (unsigned)b; sh_above = above; }
            above += h;
        }
        __syncthreads();
        if (tid == 0) {
            sh_prefix |= (sh_bin << shifts[r]);
            sh_kneed  -= sh_above;
        }
    }
    __syncthreads();
    const unsigned T    = sh_prefix;
    const unsigned krem = sh_kneed;

    #pragma unroll 4
    for (int j = 0; j < NTOK / 256; j++) {
        int i = tid + j * 256;
        float v = row[i];
        unsigned key = f2key(v);
        if (key > T) {
            int p = atomicAdd(&sel_n, 1);
            s_idx[p] = i; s_val[p] = v;
        } else if (key == T) {
            int p = atomicAdd(&tie_n, 1);
            if (p < 64) tie_buf[p] = i;
        }
    }
    __syncthreads();
    int tn = tie_n; if (tn > 64) tn = 64;
    if (tid < tn) {
        int my = tie_buf[tid], rank = 0;
        for (int j = 0; j < tn; j++) rank += (tie_buf[j] < my);
        if (rank < (int)krem) {
            int p = atomicAdd(&sel_n, 1);
            s_idx[p] = my; s_val[p] = row[my];
        }
    }
    __syncthreads();

    // softmax over the 256 selected scores
    float v = s_val[tid];
    float m = v;
    #pragma unroll
    for (int o = 16; o; o >>= 1) m = fmaxf(m, __shfl_xor_sync(0xffffffffu, m, o));
    if ((tid & 31) == 0) red[tid >> 5] = m;
    __syncthreads();
    if (tid == 0) {
        float t = red[0];
        #pragma unroll
        for (int i = 1; i < 8; i++) t = fmaxf(t, red[i]);
        red[8] = t;
    }
    __syncthreads();
    float ex = expf(v - red[8]);
    float s = ex;
    #pragma unroll
    for (int o = 16; o; o >>= 1) s += __shfl_xor_sync(0xffffffffu, s, o);
    if ((tid & 31) == 0) red[tid >> 5] = s;
    __syncthreads();
    if (tid == 0) {
        float t = 0.f;
        #pragma unroll
        for (int i = 0; i < 8; i++) t += red[i];
        red[9] = t;
    }
    __syncthreads();
    float prob = ex / red[9];

    const int n = s_idx[tid];
    g_sel_idx[e * CAP + tid]  = n;
    g_sel_prob[e * CAP + tid] = prob;
    atomicAdd(&g_counts[n], 1);
    // assignments don't depend on counts: write them here
    out[(size_t)NTOK * NEXP + (size_t)n * NEXP + e] = 1.0f;
}

// ---------------- scatter: weights = prob/count ----------------
__global__ void scatter_kernel(float* __restrict__ out) {
    int idx = blockIdx.x * blockDim.x + threadIdx.x;   // 0 .. E*CAP-1
    int e = idx >> 8;
    int n = g_sel_idx[idx];
    float p = g_sel_prob[idx];
    int c = g_counts[n];
    out[(size_t)n * NEXP + e] = p / (float)c;
}

// ---------------- launch ----------------
extern "C" void kernel_launch(void* const* d_in, const int* in_sizes, int n_in,
                              void* d_out, int out_size) {
    (void)in_sizes; (void)n_in;
    const float* hs = (const float*)d_in[0];   // hidden_states [4,4096,2048] fp32
    const float* ws = (const float*)d_in[1];   // w_sel [64,2048] fp32
    float* out = (float*)d_out;

    prep_b_kernel<<<64, 512>>>(ws);
    gemm_imma_kernel<<<NTOK / BT, 512>>>(hs, out, out_size);
    topk_kernel<<<NEXP, 256>>>(out);
    scatter_kernel<<<NEXP * CAP / 256, 256>>>(out);
}

// round 11
// speedup vs baseline: 1.0735x; 1.0735x over previous
#include <cuda_runtime.h>
#include <math.h>
#include <stdint.h>

#define NTOK 16384
#define DDIM 2048
#define NEXP 64
#define CAP  256

// GEMM tiling: 128 tok x 64 exp per CTA, chunk = 32 K-elems (one k32 mma step)
#define BT    128
#define NC32  (DDIM / 32)          // 64 chunks
#define STW   4608                 // stage words: A 3*1024 + B 3*512
// static smem: 2 stages = 36864 bytes (no cudaFuncSetAttribute needed)

#define SA 1048576.0f              // 2^20 token scale
#define SB 16777216.0f             // 2^24 w_sel scale
#define QCLAMP 8355711.0f

// ---------------- scratch (static device globals: allocation-free) ----------------
__device__ __align__(16) float    g_aff[NEXP * NTOK];       // 4 MB
__device__ __align__(16) uint32_t g_bq[NC32 * 1536];        // prepacked B, fragment-major
__device__ int   g_counts[NTOK];
__device__ int   g_sel_idx[NEXP * CAP];
__device__ float g_sel_prob[NEXP * CAP];

// ---------------- quantization ----------------
__device__ __forceinline__ void q3s(float a, float scale, int &m, int &t1, int &t2) {
    float af = fminf(fmaxf(a * scale, -QCLAMP), QCLAMP);
    m = __float2int_rn(af);
    int s0 = (m << 24) >> 24;
    t1 = (m - s0) >> 8;
    int s1 = (t1 << 24) >> 24;
    t2 = (t1 - s1) >> 8;
}
__device__ __forceinline__ uint32_t packb0(int a, int b, int c, int d) {
    return __byte_perm(__byte_perm((uint32_t)a, (uint32_t)b, 0x0040),
                       __byte_perm((uint32_t)c, (uint32_t)d, 0x0040), 0x5410);
}
// quantize float4 -> 3 limb words (w0 = highest-significance byte limb)
__device__ __forceinline__ void quant3(float4 v, float scale,
                                       uint32_t &w0, uint32_t &w1, uint32_t &w2) {
    int mx,t1x,t2x, my,t1y,t2y, mz,t1z,t2z, mw,t1w,t2w;
    q3s(v.x, scale, mx, t1x, t2x);
    q3s(v.y, scale, my, t1y, t2y);
    q3s(v.z, scale, mz, t1z, t2z);
    q3s(v.w, scale, mw, t1w, t2w);
    w0 = packb0(t2x, t2y, t2z, t2w);
    w1 = packb0(t1x, t1y, t1z, t1w);
    w2 = packb0(mx, my, mz, mw);
}
__device__ __forceinline__ void imma(int* d, const uint32_t* a, const uint32_t* b) {
    asm volatile("mma.sync.aligned.m16n8k32.row.col.s32.s8.s8.s32 "
        "{%0,%1,%2,%3}, {%4,%5,%6,%7}, {%8,%9}, {%0,%1,%2,%3};"
        : "+r"(d[0]), "+r"(d[1]), "+r"(d[2]), "+r"(d[3])
        : "r"(a[0]), "r"(a[1]), "r"(a[2]), "r"(a[3]), "r"(b[0]), "r"(b[1]));
}
__device__ __forceinline__ uint32_t smem_u32(const void* p) {
    uint32_t a;
    asm("{ .reg .u64 t; cvta.to.shared.u64 t, %1; cvt.u32.u64 %0, t; }" : "=r"(a) : "l"(p));
    return a;
}
__device__ __forceinline__ void cp_async16(uint32_t dst, const void* src) {
    asm volatile("cp.async.cg.shared.global [%0], [%1], 16;" :: "r"(dst), "l"(src) : "memory");
}
__device__ __forceinline__ void cp_commit() {
    asm volatile("cp.async.commit_group;" ::: "memory");
}
__device__ __forceinline__ void cp_wait0() {
    asm volatile("cp.async.wait_group 0;" ::: "memory");
}

// ---------------- output fill (zeros + capacity tail) + counts reset ----------------
__global__ __launch_bounds__(256) void fill_kernel(float* __restrict__ out,
                                                   long long out_size) {
    const long long NE2 = 2LL * NTOK * NEXP;               // 2097152 floats
    long long i4 = (long long)blockIdx.x * 256 + threadIdx.x;  // 524288 float4 exactly
    long long lim4 = out_size >> 2; if (lim4 > (NE2 >> 2)) lim4 = NE2 >> 2;
    if (i4 < lim4) ((float4*)out)[i4] = make_float4(0.f, 0.f, 0.f, 0.f);
    if (blockIdx.x < 64) g_counts[blockIdx.x * 256 + threadIdx.x] = 0;
    if (blockIdx.x == 0)
        for (long long i = NE2 + threadIdx.x; i < out_size; i += 256) out[i] = (float)CAP;
}

// ---------------- B prep: quantize w_sel into fragment-major limb planes ----------
// chunk c (k32): c*1536 + L*512 + (e>>3)*64 + ((e&7)*4 + (kq&3))*2 + (kq>>2)
__global__ __launch_bounds__(512) void prep_b_kernel(const float* __restrict__ wsel) {
    const int g  = blockIdx.x * 512 + threadIdx.x;         // 0..32767 float4s
    const int e  = g >> 9;
    const int d0 = (g & 511) * 4;
    float4 v = *(const float4*)&wsel[(size_t)e * DDIM + d0];
    uint32_t w0, w1, w2;
    quant3(v, SB, w0, w1, w2);
    const int c  = d0 >> 5;
    const int kq = (d0 >> 2) & 7;
    const int base = c * 1536 + (e >> 3) * 64 + ((e & 7) * 4 + (kq & 3)) * 2 + (kq >> 2);
    g_bq[base]        = w0;
    g_bq[base + 512]  = w1;
    g_bq[base + 1024] = w2;
}

// ---------------- GEMM: aff[e][n] = sum_d tok[n][d]*wsel[e][d] (6-limb int8) -------
// 512 threads, warp grid 4(m) x 4(n), warp tile 32 tok x 16 exp.
// Stage layout (words): A: L*1024 + mblock*128 + lane*4 + reg
//                       B: 3072 + L*512 + nblock*64 + lane*2 + reg
__global__ __launch_bounds__(512, 1)
void gemm_imma_kernel(const float* __restrict__ tok) {
    __shared__ __align__(16) uint32_t smem[2 * STW];       // 36864 bytes, static

    const int tid  = threadIdx.x;
    const int lane = tid & 31;
    const int w    = tid >> 5;
    const int n0   = blockIdx.x * BT;
    const int gr   = lane >> 2;
    const int ci   = lane & 3;
    const int wm   = (w & 3) * 32;
    const int wn   = (w >> 2) * 16;

    int hh[2][2][4], md[2][2][4], lo[2][2][4];
    #pragma unroll
    for (int mt = 0; mt < 2; mt++)
        #pragma unroll
        for (int nt = 0; nt < 2; nt++)
            #pragma unroll
            for (int r = 0; r < 4; r++) { hh[mt][nt][r] = 0; md[mt][nt][r] = 0; lo[mt][nt][r] = 0; }

    // A staging: thread owns row rr, k-quad qh of each 16-elem half (2 halves/chunk)
    const int rr = tid >> 2;       // 0..127
    const int qh = tid & 3;        // 0..3
    const int rb = rr & 15;
    const float* gA = &tok[(size_t)(n0 + rr) * DDIM + qh * 4];

    int addrA[2];
    #pragma unroll
    for (int j = 0; j < 2; j++)
        addrA[j] = (rr >> 4) * 128 + ((rb & 7) * 4 + qh) * 4 + (rb >> 3) + 2 * j;

    // frag base offsets
    const int fA0 = ((w & 3) * 2) * 128 + lane * 4;        // + mt*128 + L*1024
    const int fB0 = 3072 + ((w >> 2) * 2) * 64 + lane * 2; // + nt*64  + L*512

    // B async-copy: 1536 words = 384 uint4 per chunk; threads 0..383 copy one each
    const uint32_t smem_base = smem_u32(smem);
    const uint32_t dstB = smem_base + 3072u * 4u + (uint32_t)tid * 16u;

    float4 a4[2];
    a4[0] = *(const float4*)gA;
    a4[1] = *(const float4*)(gA + 16);

    // stage chunk 0 into buffer 0
    {
        if (tid < 384) cp_async16(dstB, (const uint4*)g_bq + tid);
        cp_commit();
        uint32_t* st = smem;
        #pragma unroll
        for (int j = 0; j < 2; j++) {
            uint32_t w0, w1, w2;
            quant3(a4[j], SA, w0, w1, w2);
            st[addrA[j]]        = w0;
            st[addrA[j] + 1024] = w1;
            st[addrA[j] + 2048] = w2;
        }
        cp_wait0();
    }
    __syncthreads();

    for (int c = 0; c < NC32; c++) {
        // prefetch next chunk: A into regs, B via cp.async into the other buffer
        if (c + 1 < NC32) {
            a4[0] = *(const float4*)(gA + (c + 1) * 32);
            a4[1] = *(const float4*)(gA + (c + 1) * 32 + 16);
            if (tid < 384)
                cp_async16(dstB + (uint32_t)(((c + 1) & 1) * STW) * 4u,
                           (const uint4*)&g_bq[(c + 1) * 1536] + tid);
            cp_commit();
        }

        // compute on stage c&1
        {
            const uint32_t* st = smem + (c & 1) * STW;
            uint4 af[2][3];
            uint2 bf[2][3];
            #pragma unroll
            for (int mt = 0; mt < 2; mt++)
                #pragma unroll
                for (int L = 0; L < 3; L++)
                    af[mt][L] = *(const uint4*)(st + L * 1024 + fA0 + mt * 128);
            #pragma unroll
            for (int nt = 0; nt < 2; nt++)
                #pragma unroll
                for (int L = 0; L < 3; L++)
                    bf[nt][L] = *(const uint2*)(st + L * 512 + fB0 + nt * 64);
            #pragma unroll
            for (int mt = 0; mt < 2; mt++)
                #pragma unroll
                for (int nt = 0; nt < 2; nt++) {
                    imma(hh[mt][nt], (const uint32_t*)&af[mt][0], (const uint32_t*)&bf[nt][0]);
                    imma(md[mt][nt], (const uint32_t*)&af[mt][0], (const uint32_t*)&bf[nt][1]);
                    imma(md[mt][nt], (const uint32_t*)&af[mt][1], (const uint32_t*)&bf[nt][0]);
                    imma(lo[mt][nt], (const uint32_t*)&af[mt][0], (const uint32_t*)&bf[nt][2]);
                    imma(lo[mt][nt], (const uint32_t*)&af[mt][1], (const uint32_t*)&bf[nt][1]);
                    imma(lo[mt][nt], (const uint32_t*)&af[mt][2], (const uint32_t*)&bf[nt][0]);
                }
        }

        // stage next chunk's A into the other buffer; wait for B; barrier
        if (c + 1 < NC32) {
            uint32_t* st = smem + ((c + 1) & 1) * STW;
            #pragma unroll
            for (int j = 0; j < 2; j++) {
                uint32_t w0, w1, w2;
                quant3(a4[j], SA, w0, w1, w2);
                st[addrA[j]]        = w0;
                st[addrA[j] + 1024] = w1;
                st[addrA[j] + 2048] = w2;
            }
            cp_wait0();
            __syncthreads();
        }
    }

    // epilogue: dequant, write g_aff[e][token]
    #pragma unroll
    for (int mt = 0; mt < 2; mt++) {
        const int tok0 = n0 + wm + mt * 16 + gr;
        #pragma unroll
        for (int nt = 0; nt < 2; nt++) {
            const int e0 = wn + nt * 8 + 2 * ci;
            #pragma unroll
            for (int r = 0; r < 4; r++) {
                float v = fmaf((float)hh[mt][nt][r], 0x1p-12f,
                          fmaf((float)md[mt][nt][r], 0x1p-20f,
                               (float)lo[mt][nt][r] * 0x1p-28f));
                const int tk = tok0 + ((r >> 1) << 3);
                const int ee = e0 + (r & 1);
                g_aff[(size_t)ee * NTOK + tk] = v;
            }
        }
    }
}

// ---------------- per-expert top-256 + softmax (exact fp32 radix select) ----------
__device__ __forceinline__ unsigned f2key(float v) {
    unsigned u = __float_as_uint(v);
    return (u & 0x80000000u) ? ~u : (u | 0x80000000u);
}

__global__ __launch_bounds__(256) void topk_kernel() {
    const int e   = blockIdx.x;
    const int tid = threadIdx.x;
    const float* __restrict__ row = g_aff + (size_t)e * NTOK;

    __shared__ unsigned hist[2048];
    __shared__ unsigned chunksum[257];
    __shared__ unsigned sh_prefix, sh_kneed, sh_bin, sh_above;
    __shared__ int   s_idx[CAP];
    __shared__ float s_val[CAP];
    __shared__ int   tie_buf[64];
    __shared__ int   sel_n, tie_n;
    __shared__ float red[10];

    if (tid == 0) { sh_prefix = 0u; sh_kneed = CAP; sel_n = 0; tie_n = 0; }

    const int      shifts[3]   = {21, 10, 0};
    const unsigned binmask[3]  = {2047u, 2047u, 1023u};
    const unsigned donemask[3] = {0u, 0xFFE00000u, 0xFFFFFC00u};

    for (int r = 0; r < 3; r++) {
        for (int b = tid; b < 2048; b += 256) hist[b] = 0u;
        __syncthreads();

        const unsigned pfx = sh_prefix;
        const unsigned dm  = donemask[r];
        const int      sh  = shifts[r];
        const unsigned bm  = binmask[r];

        #pragma unroll 4
        for (int j = 0; j < NTOK / 256; j++) {
            unsigned key = f2key(row[tid + j * 256]);
            if ((key & dm) == pfx) atomicAdd(&hist[(key >> sh) & bm], 1u);
        }
        __syncthreads();

        unsigned S = 0;
        #pragma unroll
        for (int q = 0; q < 8; q++) S += hist[tid * 8 + q];
        chunksum[tid] = S;
        __syncthreads();
        for (int off = 1; off < 256; off <<= 1) {
            unsigned v = (tid + off < 256) ? chunksum[tid + off] : 0u;
            __syncthreads();
            chunksum[tid] += v;
            __syncthreads();
        }
        const unsigned kneed = sh_kneed;
        unsigned above = (tid < 255) ? chunksum[tid + 1] : 0u;
        for (int b = tid * 8 + 7; b >= tid * 8; b--) {
            unsigned h = hist[b];
            if (kneed > above && kneed <= above + h) { sh_bin = (unsigned)b; sh_above = above; }
            above += h;
        }
        __syncthreads();
        if (tid == 0) {
            sh_prefix |= (sh_bin << shifts[r]);
            sh_kneed  -= sh_above;
        }
    }
    __syncthreads();
    const unsigned T    = sh_prefix;
    const unsigned krem = sh_kneed;

    #pragma unroll 4
    for (int j = 0; j < NTOK / 256; j++) {
        int i = tid + j * 256;
        float v = row[i];
        unsigned key = f2key(v);
        if (key > T) {
            int p = atomicAdd(&sel_n, 1);
            s_idx[p] = i; s_val[p] = v;
        } else if (key == T) {
            int p = atomicAdd(&tie_n, 1);
            if (p < 64) tie_buf[p] = i;
        }
    }
    __syncthreads();
    int tn = tie_n; if (tn > 64) tn = 64;
    if (tid < tn) {
        int my = tie_buf[tid], rank = 0;
        for (int j = 0; j < tn; j++) rank += (tie_buf[j] < my);
        if (rank < (int)krem) {
            int p = atomicAdd(&sel_n, 1);
            s_idx[p] = my; s_val[p] = row[my];
        }
    }
    __syncthreads();

    // softmax over the 256 selected scores
    float v = s_val[tid];
    float m = v;
    #pragma unroll
    for (int o = 16; o; o >>= 1) m = fmaxf(m, __shfl_xor_sync(0xffffffffu, m, o));
    if ((tid & 31) == 0) red[tid >> 5] = m;
    __syncthreads();
    if (tid == 0) {
        float t = red[0];
        #pragma unroll
        for (int i = 1; i < 8; i++) t = fmaxf(t, red[i]);
        red[8] = t;
    }
    __syncthreads();
    float ex = expf(v - red[8]);
    float s = ex;
    #pragma unroll
    for (int o = 16; o; o >>= 1) s += __shfl_xor_sync(0xffffffffu, s, o);
    if ((tid & 31) == 0) red[tid >> 5] = s;
    __syncthreads();
    if (tid == 0) {
        float t = 0.f;
        #pragma unroll
        for (int i = 0; i < 8; i++) t += red[i];
        red[9] = t;
    }
    __syncthreads();
    float prob = ex / red[9];

    g_sel_idx[e * CAP + tid]  = s_idx[tid];
    g_sel_prob[e * CAP + tid] = prob;
    atomicAdd(&g_counts[s_idx[tid]], 1);
}

// ---------------- scatter: weights = prob/count, assignments = 1 ----------------
__global__ void scatter_kernel(float* __restrict__ out) {
    int idx = blockIdx.x * blockDim.x + threadIdx.x;
    int e = idx >> 8;
    int n = g_sel_idx[idx];
    float p = g_sel_prob[idx];
    int c = g_counts[n];
    out[(size_t)n * NEXP + e] = p / (float)c;
    out[(size_t)NTOK * NEXP + (size_t)n * NEXP + e] = 1.0f;
}

// ---------------- launch ----------------
extern "C" void kernel_launch(void* const* d_in, const int* in_sizes, int n_in,
                              void* d_out, int out_size) {
    (void)in_sizes; (void)n_in;
    const float* hs = (const float*)d_in[0];
    const float* ws = (const float*)d_in[1];
    float* out = (float*)d_out;

    fill_kernel<<<2048, 256>>>(out, (long long)out_size);
    prep_b_kernel<<<64, 512>>>(ws);
    gemm_imma_kernel<<<NTOK / BT, 512>>>(hs);
    topk_kernel<<<NEXP, 256>>>();
    scatter_kernel<<<NEXP * CAP / 256, 256>>>(out);
}

// round 12
// speedup vs baseline: 1.2857x; 1.1977x over previous
#include <cuda_runtime.h>
#include <math.h>
#include <stdint.h>

#define NTOK 16384
#define DDIM 2048
#define NEXP 64
#define CAP  256
#define CANDMAX 3072

// GEMM tiling: 128 tok x 64 exp per CTA, chunk = 32 K-elems (one k32 mma step)
#define BT    128
#define NC32  (DDIM / 32)          // 64 chunks
#define STW   4608                 // stage words: A 3*1024 + B 3*512

#define SA 1048576.0f              // 2^20 token scale
#define SB 16777216.0f             // 2^24 w_sel scale
#define QCLAMP 8355711.0f

// ---------------- scratch (static device globals: allocation-free) ----------------
__device__ __align__(16) float    g_aff[NEXP * NTOK];       // 4 MB
__device__ __align__(16) uint32_t g_bq[NC32 * 1536];        // prepacked B, fragment-major
__device__ int   g_counts[NTOK];
__device__ int   g_sel_idx[NEXP * CAP];
__device__ float g_sel_prob[NEXP * CAP];

// ---------------- quantization ----------------
__device__ __forceinline__ void q3s(float a, float scale, int &m, int &t1, int &t2) {
    float af = fminf(fmaxf(a * scale, -QCLAMP), QCLAMP);
    m = __float2int_rn(af);
    int s0 = (m << 24) >> 24;
    t1 = (m - s0) >> 8;
    int s1 = (t1 << 24) >> 24;
    t2 = (t1 - s1) >> 8;
}
__device__ __forceinline__ uint32_t packb0(int a, int b, int c, int d) {
    return __byte_perm(__byte_perm((uint32_t)a, (uint32_t)b, 0x0040),
                       __byte_perm((uint32_t)c, (uint32_t)d, 0x0040), 0x5410);
}
__device__ __forceinline__ void quant3(float4 v, float scale,
                                       uint32_t &w0, uint32_t &w1, uint32_t &w2) {
    int mx,t1x,t2x, my,t1y,t2y, mz,t1z,t2z, mw,t1w,t2w;
    q3s(v.x, scale, mx, t1x, t2x);
    q3s(v.y, scale, my, t1y, t2y);
    q3s(v.z, scale, mz, t1z, t2z);
    q3s(v.w, scale, mw, t1w, t2w);
    w0 = packb0(t2x, t2y, t2z, t2w);
    w1 = packb0(t1x, t1y, t1z, t1w);
    w2 = packb0(mx, my, mz, mw);
}
__device__ __forceinline__ void imma(int* d, const uint32_t* a, const uint32_t* b) {
    asm volatile("mma.sync.aligned.m16n8k32.row.col.s32.s8.s8.s32 "
        "{%0,%1,%2,%3}, {%4,%5,%6,%7}, {%8,%9}, {%0,%1,%2,%3};"
        : "+r"(d[0]), "+r"(d[1]), "+r"(d[2]), "+r"(d[3])
        : "r"(a[0]), "r"(a[1]), "r"(a[2]), "r"(a[3]), "r"(b[0]), "r"(b[1]));
}
__device__ __forceinline__ uint32_t smem_u32(const void* p) {
    uint32_t a;
    asm("{ .reg .u64 t; cvta.to.shared.u64 t, %1; cvt.u32.u64 %0, t; }" : "=r"(a) : "l"(p));
    return a;
}
__device__ __forceinline__ void cp_async16(uint32_t dst, const void* src) {
    asm volatile("cp.async.cg.shared.global [%0], [%1], 16;" :: "r"(dst), "l"(src) : "memory");
}
__device__ __forceinline__ void cp_commit() {
    asm volatile("cp.async.commit_group;" ::: "memory");
}
__device__ __forceinline__ void cp_wait0() {
    asm volatile("cp.async.wait_group 0;" ::: "memory");
}

// ---------------- fused fill + B prep ----------------
// blocks [0,2048): zero out, counts reset, tail.  [2048,2176): B quant prep.
__global__ __launch_bounds__(256) void fill_prep_kernel(const float* __restrict__ wsel,
                                                        float* __restrict__ out,
                                                        long long out_size) {
    const int bid = blockIdx.x, tid = threadIdx.x;
    if (bid < 2048) {
        const long long NE2 = 2LL * NTOK * NEXP;               // 2097152 floats
        long long i4 = (long long)bid * 256 + tid;             // 524288 float4 exactly
        long long lim4 = out_size >> 2; if (lim4 > (NE2 >> 2)) lim4 = NE2 >> 2;
        if (i4 < lim4) ((float4*)out)[i4] = make_float4(0.f, 0.f, 0.f, 0.f);
        if (bid < 64) g_counts[bid * 256 + tid] = 0;
        if (bid == 0)
            for (long long i = NE2 + tid; i < out_size; i += 256) out[i] = (float)CAP;
    } else {
        const int g  = (bid - 2048) * 256 + tid;               // 0..32767 float4s
        const int e  = g >> 9;
        const int d0 = (g & 511) * 4;
        float4 v = *(const float4*)&wsel[(size_t)e * DDIM + d0];
        uint32_t w0, w1, w2;
        quant3(v, SB, w0, w1, w2);
        const int c  = d0 >> 5;
        const int kq = (d0 >> 2) & 7;
        const int base = c * 1536 + (e >> 3) * 64 + ((e & 7) * 4 + (kq & 3)) * 2 + (kq >> 2);
        g_bq[base]        = w0;
        g_bq[base + 512]  = w1;
        g_bq[base + 1024] = w2;
    }
}

// ---------------- GEMM: aff[e][n] = sum_d tok[n][d]*wsel[e][d] (6-limb int8) -------
__global__ __launch_bounds__(512, 1)
void gemm_imma_kernel(const float* __restrict__ tok) {
    __shared__ __align__(16) uint32_t smem[2 * STW];           // 36864 bytes, static

    const int tid  = threadIdx.x;
    const int lane = tid & 31;
    const int w    = tid >> 5;
    const int n0   = blockIdx.x * BT;
    const int gr   = lane >> 2;
    const int ci   = lane & 3;
    const int wm   = (w & 3) * 32;
    const int wn   = (w >> 2) * 16;

    int hh[2][2][4], md[2][2][4], lo[2][2][4];
    #pragma unroll
    for (int mt = 0; mt < 2; mt++)
        #pragma unroll
        for (int nt = 0; nt < 2; nt++)
            #pragma unroll
            for (int r = 0; r < 4; r++) { hh[mt][nt][r] = 0; md[mt][nt][r] = 0; lo[mt][nt][r] = 0; }

    const int rr = tid >> 2;
    const int qh = tid & 3;
    const int rb = rr & 15;
    const float* gA = &tok[(size_t)(n0 + rr) * DDIM + qh * 4];

    int addrA[2];
    #pragma unroll
    for (int j = 0; j < 2; j++)
        addrA[j] = (rr >> 4) * 128 + ((rb & 7) * 4 + qh) * 4 + (rb >> 3) + 2 * j;

    const int fA0 = ((w & 3) * 2) * 128 + lane * 4;
    const int fB0 = 3072 + ((w >> 2) * 2) * 64 + lane * 2;

    const uint32_t smem_base = smem_u32(smem);
    const uint32_t dstB = smem_base + 3072u * 4u + (uint32_t)tid * 16u;

    float4 a4[2];
    a4[0] = *(const float4*)gA;
    a4[1] = *(const float4*)(gA + 16);

    {
        if (tid < 384) cp_async16(dstB, (const uint4*)g_bq + tid);
        cp_commit();
        uint32_t* st = smem;
        #pragma unroll
        for (int j = 0; j < 2; j++) {
            uint32_t w0, w1, w2;
            quant3(a4[j], SA, w0, w1, w2);
            st[addrA[j]]        = w0;
            st[addrA[j] + 1024] = w1;
            st[addrA[j] + 2048] = w2;
        }
        cp_wait0();
    }
    __syncthreads();

    for (int c = 0; c < NC32; c++) {
        if (c + 1 < NC32) {
            a4[0] = *(const float4*)(gA + (c + 1) * 32);
            a4[1] = *(const float4*)(gA + (c + 1) * 32 + 16);
            if (tid < 384)
                cp_async16(dstB + (uint32_t)(((c + 1) & 1) * STW) * 4u,
                           (const uint4*)&g_bq[(c + 1) * 1536] + tid);
            cp_commit();
        }

        {
            const uint32_t* st = smem + (c & 1) * STW;
            uint4 af[2][3];
            uint2 bf[2][3];
            #pragma unroll
            for (int mt = 0; mt < 2; mt++)
                #pragma unroll
                for (int L = 0; L < 3; L++)
                    af[mt][L] = *(const uint4*)(st + L * 1024 + fA0 + mt * 128);
            #pragma unroll
            for (int nt = 0; nt < 2; nt++)
                #pragma unroll
                for (int L = 0; L < 3; L++)
                    bf[nt][L] = *(const uint2*)(st + L * 512 + fB0 + nt * 64);
            #pragma unroll
            for (int mt = 0; mt < 2; mt++)
                #pragma unroll
                for (int nt = 0; nt < 2; nt++) {
                    imma(hh[mt][nt], (const uint32_t*)&af[mt][0], (const uint32_t*)&bf[nt][0]);
                    imma(md[mt][nt], (const uint32_t*)&af[mt][0], (const uint32_t*)&bf[nt][1]);
                    imma(md[mt][nt], (const uint32_t*)&af[mt][1], (const uint32_t*)&bf[nt][0]);
                    imma(lo[mt][nt], (const uint32_t*)&af[mt][0], (const uint32_t*)&bf[nt][2]);
                    imma(lo[mt][nt], (const uint32_t*)&af[mt][1], (const uint32_t*)&bf[nt][1]);
                    imma(lo[mt][nt], (const uint32_t*)&af[mt][2], (const uint32_t*)&bf[nt][0]);
                }
        }

        if (c + 1 < NC32) {
            uint32_t* st = smem + ((c + 1) & 1) * STW;
            #pragma unroll
            for (int j = 0; j < 2; j++) {
                uint32_t w0, w1, w2;
                quant3(a4[j], SA, w0, w1, w2);
                st[addrA[j]]        = w0;
                st[addrA[j] + 1024] = w1;
                st[addrA[j] + 2048] = w2;
            }
            cp_wait0();
            __syncthreads();
        }
    }

    #pragma unroll
    for (int mt = 0; mt < 2; mt++) {
        const int tok0 = n0 + wm + mt * 16 + gr;
        #pragma unroll
        for (int nt = 0; nt < 2; nt++) {
            const int e0 = wn + nt * 8 + 2 * ci;
            #pragma unroll
            for (int r = 0; r < 4; r++) {
                float v = fmaf((float)hh[mt][nt][r], 0x1p-12f,
                          fmaf((float)md[mt][nt][r], 0x1p-20f,
                               (float)lo[mt][nt][r] * 0x1p-28f));
                const int tk = tok0 + ((r >> 1) << 3);
                const int ee = e0 + (r & 1);
                g_aff[(size_t)ee * NTOK + tk] = v;
            }
        }
    }
}

// ---------------- per-expert top-256 via candidate compaction ----------
__device__ __forceinline__ unsigned f2key(float v) {
    unsigned u = __float_as_uint(v);
    return (u & 0x80000000u) ? ~u : (u | 0x80000000u);
}

__global__ __launch_bounds__(512) void topk_kernel() {
    const int e   = blockIdx.x;
    const int tid = threadIdx.x;
    const float* __restrict__ row = g_aff + (size_t)e * NTOK;

    __shared__ unsigned hist[2048];
    __shared__ unsigned chunksum[513];
    __shared__ unsigned sh_bin, sh_above;
    __shared__ int   s_idx[CAP];
    __shared__ float s_val[CAP];
    __shared__ int   c_idx[CANDMAX];
    __shared__ float c_val[CANDMAX];
    __shared__ int   tie_buf[64];
    __shared__ int   sel_n, tie_n, ncand;
    __shared__ float red[18];

    if (tid == 0) { sel_n = 0; tie_n = 0; ncand = 0; }
    for (int b = tid; b < 2048; b += 512) hist[b] = 0u;
    __syncthreads();

    // ---- round 1: histogram over top 11 bits (full row, pass 1) ----
    #pragma unroll 4
    for (int j = 0; j < NTOK / 512; j++) {
        unsigned key = f2key(row[tid + j * 512]);
        atomicAdd(&hist[key >> 21], 1u);
    }
    __syncthreads();

    unsigned S = hist[tid * 4] + hist[tid * 4 + 1] + hist[tid * 4 + 2] + hist[tid * 4 + 3];
    chunksum[tid] = S;
    __syncthreads();
    for (int off = 1; off < 512; off <<= 1) {
        unsigned v = (tid + off < 512) ? chunksum[tid + off] : 0u;
        __syncthreads();
        chunksum[tid] += v;
        __syncthreads();
    }
    {
        unsigned above = (tid < 511) ? chunksum[tid + 1] : 0u;
        for (int b = tid * 4 + 3; b >= tid * 4; b--) {
            unsigned h = hist[b];
            if ((unsigned)CAP > above && (unsigned)CAP <= above + h) { sh_bin = (unsigned)b; sh_above = above; }
            above += h;
        }
    }
    __syncthreads();
    const unsigned pb = sh_bin;
    unsigned kneed = CAP - sh_above;

    // ---- pass 2: compact — accept key-bin > pb, buffer key-bin == pb ----
    #pragma unroll 2
    for (int j = 0; j < NTOK / 512; j++) {
        int i = tid + j * 512;
        float v = row[i];
        unsigned key = f2key(v);
        unsigned b = key >> 21;
        if (b > pb) {
            int p = atomicAdd(&sel_n, 1);
            s_idx[p] = i; s_val[p] = v;
        } else if (b == pb) {
            int p = atomicAdd(&ncand, 1);
            if (p < CANDMAX) { c_idx[p] = i; c_val[p] = v; }
        }
    }
    __syncthreads();
    const int nc = ncand < CANDMAX ? ncand : CANDMAX;
    for (int b = tid; b < 2048; b += 512) hist[b] = 0u;
    __syncthreads();

    // ---- round 2 on candidates: bits [10,21) ----
    for (int p = tid; p < nc; p += 512)
        atomicAdd(&hist[(f2key(c_val[p]) >> 10) & 2047u], 1u);
    __syncthreads();
    S = hist[tid * 4] + hist[tid * 4 + 1] + hist[tid * 4 + 2] + hist[tid * 4 + 3];
    chunksum[tid] = S;
    __syncthreads();
    for (int off = 1; off < 512; off <<= 1) {
        unsigned v = (tid + off < 512) ? chunksum[tid + off] : 0u;
        __syncthreads();
        chunksum[tid] += v;
        __syncthreads();
    }
    {
        unsigned above = (tid < 511) ? chunksum[tid + 1] : 0u;
        for (int b = tid * 4 + 3; b >= tid * 4; b--) {
            unsigned h = hist[b];
            if (kneed > above && kneed <= above + h) { sh_bin = (unsigned)b; sh_above = above; }
            above += h;
        }
    }
    __syncthreads();
    const unsigned pb2 = sh_bin;
    kneed -= sh_above;
    __syncthreads();
    for (int b = tid; b < 2048; b += 512) hist[b] = 0u;
    __syncthreads();

    // ---- round 3 on candidates within pb2: bits [0,10) ----
    for (int p = tid; p < nc; p += 512) {
        unsigned key = f2key(c_val[p]);
        if (((key >> 10) & 2047u) == pb2) atomicAdd(&hist[key & 1023u], 1u);
    }
    __syncthreads();
    S = hist[tid * 2] + hist[tid * 2 + 1];
    chunksum[tid] = S;
    __syncthreads();
    for (int off = 1; off < 512; off <<= 1) {
        unsigned v = (tid + off < 512) ? chunksum[tid + off] : 0u;
        __syncthreads();
        chunksum[tid] += v;
        __syncthreads();
    }
    {
        unsigned above = (tid < 511) ? chunksum[tid + 1] : 0u;
        for (int b = tid * 2 + 1; b >= tid * 2; b--) {
            unsigned h = hist[b];
            if (kneed > above && kneed <= above + h) { sh_bin = (unsigned)b; sh_above = above; }
            above += h;
        }
    }
    __syncthreads();
    const unsigned T    = (pb << 21) | (pb2 << 10) | sh_bin;
    const unsigned krem = kneed - sh_above;

    // ---- final collection over candidates ----
    for (int p = tid; p < nc; p += 512) {
        float v = c_val[p];
        unsigned key = f2key(v);
        if (key > T) {
            int q = atomicAdd(&sel_n, 1);
            s_idx[q] = c_idx[p]; s_val[q] = v;
        } else if (key == T) {
            int q = atomicAdd(&tie_n, 1);
            if (q < 64) tie_buf[q] = c_idx[p];
        }
    }
    __syncthreads();
    int tn = tie_n; if (tn > 64) tn = 64;
    if (tid < tn) {
        int my = tie_buf[tid], rank = 0;
        for (int j = 0; j < tn; j++) rank += (tie_buf[j] < my);
        if (rank < (int)krem) {
            int q = atomicAdd(&sel_n, 1);
            s_idx[q] = my; s_val[q] = row[my];
        }
    }
    __syncthreads();

    // ---- softmax over the 256 selected (threads 0..255 own one entry) ----
    float vv = (tid < 256) ? s_val[tid] : -INFINITY;
    float m = vv;
    #pragma unroll
    for (int o = 16; o; o >>= 1) m = fmaxf(m, __shfl_xor_sync(0xffffffffu, m, o));
    if ((tid & 31) == 0) red[tid >> 5] = m;
    __syncthreads();
    if (tid == 0) {
        float t = red[0];
        #pragma unroll
        for (int i = 1; i < 8; i++) t = fmaxf(t, red[i]);
        red[16] = t;
    }
    __syncthreads();
    float ex = (tid < 256) ? expf(vv - red[16]) : 0.f;
    float s = ex;
    #pragma unroll
    for (int o = 16; o; o >>= 1) s += __shfl_xor_sync(0xffffffffu, s, o);
    if ((tid & 31) == 0) red[tid >> 5] = s;
    __syncthreads();
    if (tid == 0) {
        float t = 0.f;
        #pragma unroll
        for (int i = 0; i < 8; i++) t += red[i];
        red[17] = t;
    }
    __syncthreads();

    if (tid < 256) {
        float prob = ex / red[17];
        g_sel_idx[e * CAP + tid]  = s_idx[tid];
        g_sel_prob[e * CAP + tid] = prob;
        atomicAdd(&g_counts[s_idx[tid]], 1);
    }
}

// ---------------- scatter: weights = prob/count, assignments = 1 ----------------
__global__ void scatter_kernel(float* __restrict__ out) {
    int idx = blockIdx.x * blockDim.x + threadIdx.x;
    int e = idx >> 8;
    int n = g_sel_idx[idx];
    float p = g_sel_prob[idx];
    int c = g_counts[n];
    out[(size_t)n * NEXP + e] = p / (float)c;
    out[(size_t)NTOK * NEXP + (size_t)n * NEXP + e] = 1.0f;
}

// ---------------- launch ----------------
extern "C" void kernel_launch(void* const* d_in, const int* in_sizes, int n_in,
                              void* d_out, int out_size) {
    (void)in_sizes; (void)n_in;
    const float* hs = (const float*)d_in[0];
    const float* ws = (const float*)d_in[1];
    float* out = (float*)d_out;

    fill_prep_kernel<<<2176, 256>>>(ws, out, (long long)out_size);
    gemm_imma_kernel<<<NTOK / BT, 512>>>(hs);
    topk_kernel<<<NEXP, 512>>>();
    scatter_kernel<<<NEXP * CAP / 256, 256>>>(out);
}